// round 11
// baseline (speedup 1.0000x reference)
#include <cuda_runtime.h>
#include <stdint.h>
#include <math.h>

#define NB 256
#define TOK (NB*64)

__device__ float g_Wp[1024*1024];
__device__ float g_Xp[(size_t)TOK*1024];
__device__ float g_PV[(size_t)TOK*1024];

__device__ __forceinline__ float to_tf32(float x){ float r; asm("cvt.rna.tf32.f32 %0, %1;" : "=f"(r) : "f"(x)); return r; }
__device__ __forceinline__ uint32_t fb(float x){ return __float_as_uint(x); }
__device__ __forceinline__ void mma8(float* c, const uint32_t* a, const uint32_t* b){
    asm volatile("mma.sync.aligned.m16n8k8.row.col.f32.tf32.tf32.f32 "
        "{%0,%1,%2,%3}, {%4,%5,%6,%7}, {%8,%9}, {%0,%1,%2,%3};"
        : "+f"(c[0]), "+f"(c[1]), "+f"(c[2]), "+f"(c[3])
        : "r"(a[0]), "r"(a[1]), "r"(a[2]), "r"(a[3]), "r"(b[0]), "r"(b[1]));
}
__device__ __forceinline__ float wmax(float v){
    #pragma unroll
    for (int o=16;o>0;o>>=1) v = fmaxf(v, __shfl_xor_sync(0xffffffffu,v,o));
    return v;
}
__device__ __forceinline__ float wsum(float v){
    #pragma unroll
    for (int o=16;o>0;o>>=1) v += __shfl_xor_sync(0xffffffffu,v,o);
    return v;
}
__device__ __forceinline__ uint32_t smem_u32(const void* p){
    uint32_t a; asm("{ .reg .u64 t; cvta.to.shared.u64 t, %1; cvt.u32.u64 %0, t; }" : "=r"(a) : "l"(p));
    return a;
}
__device__ __forceinline__ void cpa16(uint32_t dst, const void* src){
    asm volatile("cp.async.cg.shared.global [%0], [%1], 16;" :: "r"(dst), "l"(src) : "memory");
}
__device__ __forceinline__ void cpa_commit(){ asm volatile("cp.async.commit_group;" ::: "memory"); }

// ============================================================
// K0: prep — merge h|z, tf32-round, pair-permute into g_Xp.
// ============================================================
__global__ __launch_bounds__(256,8) void k_prep(
    const float* __restrict__ h, const float* __restrict__ z)
{
    int idx = blockIdx.x*256 + threadIdx.x;
    int t = idx >> 7, g = idx & 127;
    const float* X = (g < 64) ? h : z;
    const float* p = X + (size_t)t*512 + (g & 63)*8;
    float4 v0 = *(const float4*)p;
    float4 v1 = *(const float4*)(p + 4);
    float4 o0, o1;
    o0.x = to_tf32(v0.x); o0.y = to_tf32(v1.x);
    o0.z = to_tf32(v0.y); o0.w = to_tf32(v1.y);
    o1.x = to_tf32(v0.z); o1.y = to_tf32(v1.z);
    o1.z = to_tf32(v0.w); o1.w = to_tf32(v1.w);
    float* dst = g_Xp + (size_t)t*1024 + g*8;
    *(float4*)dst = o0;
    *(float4*)(dst + 4) = o1;
}

// ============================================================
// K1: fused weight precompute, tf32 mma, merged. grid 64, 256 thr.
// ============================================================
#define FU_A_FLOATS (32*136)
#define FU_B_FLOATS (128*36)
#define FU_STF      (FU_A_FLOATS + FU_B_FLOATS)
#define FU_SMEM_BYTES (3*FU_STF*4)

extern __shared__ float fusm[];

__global__ __launch_bounds__(256,1) void k_fuse_tc(
    const float* __restrict__ Whk, const float* __restrict__ Wzk,
    const float* __restrict__ Whv, const float* __restrict__ Wzv,
    const float* __restrict__ Wq,  const float* __restrict__ Wo)
{
    const int tid = threadIdx.x, lane = tid&31, wid = tid>>5;
    const int q = lane>>2, s = lane&3;
    const int BT = blockIdx.x >> 5;
    const int qd = (blockIdx.x >> 4) & 1;
    const int tile = blockIdx.x & 15;
    const float* Ap; const float* Bp;
    if (BT == 0){ Ap = qd ? Wzk : Whk; Bp = qd ? (Wq + 1024*512) : Wq; }
    else        { Ap = qd ? Wzv : Whv; Bp = qd ? (Wo + 1024) : Wo; }
    const int row0 = qd*512, col0 = BT*512;
    const float scale = BT ? 1.f : 0.04419417382415922f;
    const int m0 = (tile>>2)*128, n0 = (tile&3)*128;
    const int wm = (wid>>2)*64, wn = (wid&3)*32;

    float* stA[3]; float* stB[3];
    #pragma unroll
    for (int ss=0;ss<3;ss++){ stA[ss] = fusm + ss*FU_STF; stB[ss] = stA[ss] + FU_A_FLOATS; }

    float acc[4][4][4];
    #pragma unroll
    for (int a=0;a<4;a++)
        #pragma unroll
        for (int b=0;b<4;b++)
            #pragma unroll
            for (int c=0;c<4;c++) acc[a][b][c]=0.f;

    auto fill = [&](int c){
        const int si = c%3;
        const int kc = c*32;
        float* A = stA[si]; float* B = stB[si];
        #pragma unroll
        for (int i=0;i<4;i++){
            int u = tid + 256*i;
            int e = u>>5, j = u&31;
            cpa16(smem_u32(A + e*136 + j*4), Ap + (size_t)(kc+e)*512 + m0 + j*4);
        }
        if (BT == 0){
            #pragma unroll
            for (int i=0;i<4;i++){
                int u = tid + 256*i;
                int e = u>>5, j = u&31;
                cpa16(smem_u32(B + e*136 + j*4), Bp + (size_t)(kc+e)*512 + n0 + j*4);
            }
        } else {
            #pragma unroll
            for (int i=0;i<4;i++){
                int u = tid + 256*i;
                int n = u>>3, j = u&7;
                cpa16(smem_u32(B + n*36 + j*4), Bp + (size_t)(n0+n)*2048 + kc + j*4);
            }
        }
        cpa_commit();
    };

    fill(0); fill(1);

    for (int c = 0; c < 32; c++){
        if (c < 31) asm volatile("cp.async.wait_group 1;" ::: "memory");
        else        asm volatile("cp.async.wait_group 0;" ::: "memory");
        __syncthreads();
        if (c < 30) fill(c+2);

        const float* A = stA[c%3];
        const float* B = stB[c%3];
        #pragma unroll
        for (int ks=0; ks<4; ks++){
            const int k0 = ks*8 + s;
            uint32_t bf[4][2];
            #pragma unroll
            for (int nf=0; nf<4; nf++){
                int cn = wn + nf*8 + q;
                if (BT == 0){
                    bf[nf][0] = fb(to_tf32(B[k0*136 + cn]));
                    bf[nf][1] = fb(to_tf32(B[(k0+4)*136 + cn]));
                } else {
                    bf[nf][0] = fb(to_tf32(B[cn*36 + k0]));
                    bf[nf][1] = fb(to_tf32(B[cn*36 + k0 + 4]));
                }
            }
            uint32_t af[4][4];
            #pragma unroll
            for (int mf=0; mf<4; mf++){
                int r = wm + mf*16 + q;
                af[mf][0] = fb(to_tf32(A[k0*136 + r]));
                af[mf][1] = fb(to_tf32(A[k0*136 + r + 8]));
                af[mf][2] = fb(to_tf32(A[(k0+4)*136 + r]));
                af[mf][3] = fb(to_tf32(A[(k0+4)*136 + r + 8]));
            }
            #pragma unroll
            for (int mf=0; mf<4; mf++)
                #pragma unroll
                for (int nf=0; nf<4; nf++)
                    mma8(acc[mf][nf], af[mf], bf[nf]);
        }
    }

    #pragma unroll
    for (int mf=0; mf<4; mf++){
        int M = row0 + m0 + wm + mf*16 + q;
        #pragma unroll
        for (int nf=0; nf<4; nf++){
            int N = col0 + n0 + wn + nf*8 + s*2;
            #pragma unroll
            for (int e=0; e<4; e++){
                int Mx = M + ((e>>1)<<3);
                int Nx = N + (e&1);
                g_Wp[(size_t)Nx*1024 + ((Mx>>3)<<3) + ((Mx&3)<<1) + ((Mx>>2)&1)]
                    = to_tf32(scale*acc[mf][nf][e]);
            }
        }
    }
}

// ============================================================
// K2 v3: PV = X @ Wp^T. A in smem (2-stage cp.async, swizzled);
// B-frags direct LDG.64 from L2-resident pair-packed g_Wp.
// CTA 128x128, 256 thr, warps 2m x 4n (64x32), 2 CTAs/SM, grid (8,128).
// ============================================================
#define PV_STG (128*32)
#define PV_SMEM_BYTES (2*PV_STG*4)

extern __shared__ float pvsm[];

__global__ __launch_bounds__(256,2) void k_pv()
{
    const int tid = threadIdx.x, lane = tid&31, wid = tid>>5;
    const int q = lane>>2, s = lane&3;
    const int m0 = blockIdx.y*128, n0 = blockIdx.x*128;
    const int wm = (wid>>2)*64, wn = (wid&3)*32;

    float* stA[2] = { pvsm, pvsm + PV_STG };

    int poff[4];
    #pragma unroll
    for (int ks=0;ks<4;ks++) poff[ks] = (((ks*2 + (s>>1)) ^ q) << 2) + ((s&1) << 1);

    float acc[4][4][4];
    #pragma unroll
    for (int a=0;a<4;a++)
        #pragma unroll
        for (int b=0;b<4;b++)
            #pragma unroll
            for (int c=0;c<4;c++) acc[a][b][c]=0.f;

    auto fill = [&](int c){
        float* A = stA[c&1];
        #pragma unroll
        for (int i=0;i<4;i++){
            int u = tid + 256*i;
            int r = u>>3, j = u&7;
            cpa16(smem_u32(A + r*32 + ((j ^ (r&7))<<2)),
                  g_Xp + (size_t)(m0+r)*1024 + c*32 + j*4);
        }
        cpa_commit();
    };

    const float* Bw = g_Wp + (size_t)(n0 + wn + q)*1024 + s*2;

    fill(0); fill(1);

    for (int c = 0; c < 32; c++){
        if (c < 31) asm volatile("cp.async.wait_group 1;" ::: "memory");
        else        asm volatile("cp.async.wait_group 0;" ::: "memory");
        __syncthreads();

        const float* A = stA[c&1];
        const float* Bc = Bw + c*32;
        #pragma unroll
        for (int ks=0; ks<4; ks++){
            float2 bv[4];
            #pragma unroll
            for (int nf=0; nf<4; nf++)
                bv[nf] = __ldg((const float2*)(Bc + nf*8192 + ks*8));
            uint32_t af[4][4];
            #pragma unroll
            for (int mf=0; mf<4; mf++){
                int ra = wm + mf*16 + q;
                const float* ap = A + ra*32;
                float2 lo = *(const float2*)(ap + poff[ks]);
                float2 hi = *(const float2*)(ap + 256 + poff[ks]);
                af[mf][0] = fb(lo.x); af[mf][1] = fb(hi.x);
                af[mf][2] = fb(lo.y); af[mf][3] = fb(hi.y);
            }
            #pragma unroll
            for (int mf=0; mf<4; mf++)
                #pragma unroll
                for (int nf=0; nf<4; nf++){
                    uint32_t bf[2]; bf[0] = fb(bv[nf].x); bf[1] = fb(bv[nf].y);
                    mma8(acc[mf][nf], af[mf], bf);
                }
        }
        __syncthreads();
        if (c < 30) fill(c+2);
    }

    #pragma unroll
    for (int mf=0; mf<4; mf++){
        int m = m0 + wm + mf*16 + q;
        #pragma unroll
        for (int nf=0; nf<4; nf++){
            int n = n0 + wn + nf*8 + s*2;
            float2 v0; v0.x = acc[mf][nf][0]; v0.y = acc[mf][nf][1];
            float2 v1; v1.x = acc[mf][nf][2]; v1.y = acc[mf][nf][3];
            *(float2*)(g_PV + (size_t)m*1024 + n)     = v0;
            *(float2*)(g_PV + (size_t)(m+8)*1024 + n) = v1;
        }
    }
}

// ============================================================
// K3: per-batch attention + LN (unchanged from R8, measured 87.7us).
// ============================================================
#define AT_LS   0
#define AT_GS   (64*68)
#define AT_BS   (AT_GS + 512)
#define AT_OV   (AT_BS + 512)
#define AT_SMEM_FLOATS (AT_OV + 8704 + 64*516)
#define AT_SMEM_BYTES  (AT_SMEM_FLOATS*4)

extern __shared__ float atsm[];

__global__ __launch_bounds__(512,1) void k_attn_tc(
    const float* __restrict__ h, const float* __restrict__ lng,
    const float* __restrict__ lnb, float* __restrict__ out)
{
    float* ls = atsm + AT_LS;
    float* gs = atsm + AT_GS;
    float* bs = atsm + AT_BS;
    float* Pc = atsm + AT_OV;
    float* hc = Pc + 64*132;
    float* Vt = atsm + AT_OV;
    float* Ob = Vt + 128*68;

    const int b = blockIdx.x;
    const int tid = threadIdx.x, lane = tid&31, wid = tid>>5;
    const int g = lane>>2, t = lane&3;
    const float* Pb = g_PV + (size_t)b*64*1024;
    const float* hb = h + (size_t)b*64*512;

    gs[tid] = lng[tid];
    bs[tid] = lnb[tid];

    const int wlm = (wid&3)*16, wln = (wid>>2)*16;
    float lacc[2][4];
    #pragma unroll
    for (int i=0;i<2;i++)
        #pragma unroll
        for (int j=0;j<4;j++) lacc[i][j]=0.f;

    for (int dc=0; dc<4; dc++){
        #pragma unroll
        for (int it=0; it<4; it++){
            int v = tid + it*512;
            int qq = v>>5, f4 = (v&31)*4;
            float4 pv = *(const float4*)(Pb + (size_t)qq*1024 + dc*128 + f4);
            float4 cv; cv.x=to_tf32(pv.x); cv.y=to_tf32(pv.y); cv.z=to_tf32(pv.z); cv.w=to_tf32(pv.w);
            *(float4*)(Pc + qq*132 + f4) = cv;
            float4 hv = *(const float4*)(hb + (size_t)qq*512 + dc*128 + f4);
            float4 ch; ch.x=to_tf32(hv.x); ch.y=to_tf32(hv.y); ch.z=to_tf32(hv.z); ch.w=to_tf32(hv.w);
            *(float4*)(hc + qq*132 + f4) = ch;
        }
        __syncthreads();
        #pragma unroll
        for (int kk=0; kk<16; kk++){
            uint32_t af[4];
            af[0] = fb(Pc[(wlm+g)*132 + kk*8 + t]);
            af[1] = fb(Pc[(wlm+g+8)*132 + kk*8 + t]);
            af[2] = fb(Pc[(wlm+g)*132 + kk*8 + t + 4]);
            af[3] = fb(Pc[(wlm+g+8)*132 + kk*8 + t + 4]);
            #pragma unroll
            for (int nf=0; nf<2; nf++){
                uint32_t bf[2];
                bf[0] = fb(hc[(wln+nf*8+g)*132 + kk*8 + t]);
                bf[1] = fb(hc[(wln+nf*8+g)*132 + kk*8 + t + 4]);
                mma8(lacc[nf], af, bf);
            }
        }
        __syncthreads();
    }
    #pragma unroll
    for (int nf=0; nf<2; nf++){
        int col = wln + nf*8 + 2*t;
        float2 v0; v0.x = lacc[nf][0]; v0.y = lacc[nf][1];
        float2 v1; v1.x = lacc[nf][2]; v1.y = lacc[nf][3];
        *(float2*)(ls + (wlm+g)*68 + col)   = v0;
        *(float2*)(ls + (wlm+g+8)*68 + col) = v1;
    }
    __syncthreads();

    #pragma unroll
    for (int i=0;i<4;i++){
        int r = wid*4 + i;
        float v0 = ls[r*68 + lane], v1 = ls[r*68 + lane + 32];
        float m = wmax(fmaxf(v0, v1));
        float e0 = __expf(v0 - m), e1 = __expf(v1 - m);
        float inv = 1.f / wsum(e0 + e1);
        ls[r*68 + lane] = e0*inv;
        ls[r*68 + lane + 32] = e1*inv;
    }
    __syncthreads();

    const int wk = wid>>2, wd = wid&3;
    for (int dc=0; dc<4; dc++){
        #pragma unroll
        for (int it=0; it<4; it++){
            int v = tid + it*512;
            int qq = v & 63, fg = (v>>6)*4;
            float4 vv = *(const float4*)(Pb + (size_t)qq*1024 + 512 + dc*128 + fg);
            Vt[(fg+0)*68 + qq] = to_tf32(vv.x);
            Vt[(fg+1)*68 + qq] = to_tf32(vv.y);
            Vt[(fg+2)*68 + qq] = to_tf32(vv.z);
            Vt[(fg+3)*68 + qq] = to_tf32(vv.w);
        }
        __syncthreads();
        float oc[4][4];
        #pragma unroll
        for (int i=0;i<4;i++)
            #pragma unroll
            for (int j=0;j<4;j++) oc[i][j]=0.f;
        #pragma unroll
        for (int kk=0; kk<8; kk++){
            uint32_t af[4];
            af[0] = fb(ls[(wk*16+g)*68 + kk*8 + t]);
            af[1] = fb(ls[(wk*16+g+8)*68 + kk*8 + t]);
            af[2] = fb(ls[(wk*16+g)*68 + kk*8 + t + 4]);
            af[3] = fb(ls[(wk*16+g+8)*68 + kk*8 + t + 4]);
            #pragma unroll
            for (int nf=0; nf<4; nf++){
                uint32_t bf[2];
                bf[0] = fb(Vt[(wd*32+nf*8+g)*68 + kk*8 + t]);
                bf[1] = fb(Vt[(wd*32+nf*8+g)*68 + kk*8 + t + 4]);
                mma8(oc[nf], af, bf);
            }
        }
        #pragma unroll
        for (int nf=0; nf<4; nf++){
            int col = dc*128 + wd*32 + nf*8 + 2*t;
            float2 v0; v0.x = oc[nf][0]; v0.y = oc[nf][1];
            float2 v1; v1.x = oc[nf][2]; v1.y = oc[nf][3];
            *(float2*)(Ob + (wk*16+g)*516 + col)   = v0;
            *(float2*)(Ob + (wk*16+g+8)*516 + col) = v1;
        }
        __syncthreads();
    }

    {
        int row = tid>>3, j = tid&7;
        const float* orow = Ob + row*516 + j*64;
        float s1=0.f, s2=0.f;
        #pragma unroll
        for (int i2=0;i2<64;i2+=4){
            float4 v = *(const float4*)(orow+i2);
            s1 += v.x+v.y+v.z+v.w;
            s2 += v.x*v.x+v.y*v.y+v.z*v.z+v.w*v.w;
        }
        #pragma unroll
        for (int o=1;o<8;o<<=1){
            s1 += __shfl_xor_sync(0xffffffffu, s1, o);
            s2 += __shfl_xor_sync(0xffffffffu, s2, o);
        }
        float mu = s1 * (1.f/512.f);
        float var = s2 * (1.f/512.f) - mu*mu;
        float rs = rsqrtf(var + 1e-5f);
        float* op = out + ((size_t)b*64 + row)*512 + j*64;
        #pragma unroll
        for (int i2=0;i2<64;i2+=4){
            float4 v = *(const float4*)(orow+i2);
            float4 gg = *(const float4*)(gs + j*64 + i2);
            float4 bb = *(const float4*)(bs + j*64 + i2);
            float4 r;
            r.x = (v.x-mu)*rs*gg.x + bb.x;
            r.y = (v.y-mu)*rs*gg.y + bb.y;
            r.z = (v.z-mu)*rs*gg.z + bb.z;
            r.w = (v.w-mu)*rs*gg.w + bb.w;
            *(float4*)(op+i2) = r;
        }
    }
}

extern "C" void kernel_launch(void* const* d_in, const int* in_sizes, int n_in,
                              void* d_out, int out_size) {
    const float* h   = (const float*)d_in[0];
    const float* z   = (const float*)d_in[1];
    const float* Whk = (const float*)d_in[2];
    const float* Whv = (const float*)d_in[3];
    const float* Wzk = (const float*)d_in[4];
    const float* Wzv = (const float*)d_in[5];
    const float* Wq  = (const float*)d_in[6];
    const float* Wo  = (const float*)d_in[7];
    const float* lng = (const float*)d_in[8];
    const float* lnb = (const float*)d_in[9];
    float* out = (float*)d_out;

    cudaFuncSetAttribute(k_fuse_tc, cudaFuncAttributeMaxDynamicSharedMemorySize, FU_SMEM_BYTES);
    cudaFuncSetAttribute(k_pv,      cudaFuncAttributeMaxDynamicSharedMemorySize, PV_SMEM_BYTES);
    cudaFuncSetAttribute(k_attn_tc, cudaFuncAttributeMaxDynamicSharedMemorySize, AT_SMEM_BYTES);

    k_prep<<<8192, 256>>>(h, z);
    k_fuse_tc<<<64, 256, FU_SMEM_BYTES>>>(Whk, Wzk, Whv, Wzv, Wq, Wo);
    k_pv<<<dim3(8,128), 256, PV_SMEM_BYTES>>>();
    k_attn_tc<<<256, 512, AT_SMEM_BYTES>>>(h, lng, lnb, out);
}

// round 12
// speedup vs baseline: 1.2134x; 1.2134x over previous
#include <cuda_runtime.h>
#include <stdint.h>
#include <math.h>

#define NB 256
#define TOK (NB*64)

__device__ float g_Wp[1024*1024];
__device__ float g_Xp[(size_t)TOK*1024];
__device__ float g_PV[(size_t)TOK*1024];

__device__ __forceinline__ float to_tf32(float x){ float r; asm("cvt.rna.tf32.f32 %0, %1;" : "=f"(r) : "f"(x)); return r; }
__device__ __forceinline__ uint32_t fb(float x){ return __float_as_uint(x); }
__device__ __forceinline__ void mma8(float* c, const uint32_t* a, const uint32_t* b){
    asm volatile("mma.sync.aligned.m16n8k8.row.col.f32.tf32.tf32.f32 "
        "{%0,%1,%2,%3}, {%4,%5,%6,%7}, {%8,%9}, {%0,%1,%2,%3};"
        : "+f"(c[0]), "+f"(c[1]), "+f"(c[2]), "+f"(c[3])
        : "r"(a[0]), "r"(a[1]), "r"(a[2]), "r"(a[3]), "r"(b[0]), "r"(b[1]));
}
__device__ __forceinline__ float wmax(float v){
    #pragma unroll
    for (int o=16;o>0;o>>=1) v = fmaxf(v, __shfl_xor_sync(0xffffffffu,v,o));
    return v;
}
__device__ __forceinline__ float wsum(float v){
    #pragma unroll
    for (int o=16;o>0;o>>=1) v += __shfl_xor_sync(0xffffffffu,v,o);
    return v;
}
__device__ __forceinline__ uint32_t smem_u32(const void* p){
    uint32_t a; asm("{ .reg .u64 t; cvta.to.shared.u64 t, %1; cvt.u32.u64 %0, t; }" : "=r"(a) : "l"(p));
    return a;
}
__device__ __forceinline__ void cpa16(uint32_t dst, const void* src){
    asm volatile("cp.async.cg.shared.global [%0], [%1], 16;" :: "r"(dst), "l"(src) : "memory");
}
__device__ __forceinline__ void cpa_commit(){ asm volatile("cp.async.commit_group;" ::: "memory"); }

// ============================================================
// K0: prep — merge h|z, tf32-round, pair-permute into g_Xp.
// ============================================================
__global__ __launch_bounds__(256,8) void k_prep(
    const float* __restrict__ h, const float* __restrict__ z)
{
    int idx = blockIdx.x*256 + threadIdx.x;
    int t = idx >> 7, g = idx & 127;
    const float* X = (g < 64) ? h : z;
    const float* p = X + (size_t)t*512 + (g & 63)*8;
    float4 v0 = *(const float4*)p;
    float4 v1 = *(const float4*)(p + 4);
    float4 o0, o1;
    o0.x = to_tf32(v0.x); o0.y = to_tf32(v1.x);
    o0.z = to_tf32(v0.y); o0.w = to_tf32(v1.y);
    o1.x = to_tf32(v0.z); o1.y = to_tf32(v1.z);
    o1.z = to_tf32(v0.w); o1.w = to_tf32(v1.w);
    float* dst = g_Xp + (size_t)t*1024 + g*8;
    *(float4*)dst = o0;
    *(float4*)(dst + 4) = o1;
}

// ============================================================
// K1: fused weight precompute, tf32 mma, merged. grid 64, 256 thr.
// ============================================================
#define FU_A_FLOATS (32*136)
#define FU_B_FLOATS (128*36)
#define FU_STF      (FU_A_FLOATS + FU_B_FLOATS)
#define FU_SMEM_BYTES (3*FU_STF*4)

extern __shared__ float fusm[];

__global__ __launch_bounds__(256,1) void k_fuse_tc(
    const float* __restrict__ Whk, const float* __restrict__ Wzk,
    const float* __restrict__ Whv, const float* __restrict__ Wzv,
    const float* __restrict__ Wq,  const float* __restrict__ Wo)
{
    const int tid = threadIdx.x, lane = tid&31, wid = tid>>5;
    const int q = lane>>2, s = lane&3;
    const int BT = blockIdx.x >> 5;
    const int qd = (blockIdx.x >> 4) & 1;
    const int tile = blockIdx.x & 15;
    const float* Ap; const float* Bp;
    if (BT == 0){ Ap = qd ? Wzk : Whk; Bp = qd ? (Wq + 1024*512) : Wq; }
    else        { Ap = qd ? Wzv : Whv; Bp = qd ? (Wo + 1024) : Wo; }
    const int row0 = qd*512, col0 = BT*512;
    const float scale = BT ? 1.f : 0.04419417382415922f;
    const int m0 = (tile>>2)*128, n0 = (tile&3)*128;
    const int wm = (wid>>2)*64, wn = (wid&3)*32;

    float* stA[3]; float* stB[3];
    #pragma unroll
    for (int ss=0;ss<3;ss++){ stA[ss] = fusm + ss*FU_STF; stB[ss] = stA[ss] + FU_A_FLOATS; }

    float acc[4][4][4];
    #pragma unroll
    for (int a=0;a<4;a++)
        #pragma unroll
        for (int b=0;b<4;b++)
            #pragma unroll
            for (int c=0;c<4;c++) acc[a][b][c]=0.f;

    auto fill = [&](int c){
        const int si = c%3;
        const int kc = c*32;
        float* A = stA[si]; float* B = stB[si];
        #pragma unroll
        for (int i=0;i<4;i++){
            int u = tid + 256*i;
            int e = u>>5, j = u&31;
            cpa16(smem_u32(A + e*136 + j*4), Ap + (size_t)(kc+e)*512 + m0 + j*4);
        }
        if (BT == 0){
            #pragma unroll
            for (int i=0;i<4;i++){
                int u = tid + 256*i;
                int e = u>>5, j = u&31;
                cpa16(smem_u32(B + e*136 + j*4), Bp + (size_t)(kc+e)*512 + n0 + j*4);
            }
        } else {
            #pragma unroll
            for (int i=0;i<4;i++){
                int u = tid + 256*i;
                int n = u>>3, j = u&7;
                cpa16(smem_u32(B + n*36 + j*4), Bp + (size_t)(n0+n)*2048 + kc + j*4);
            }
        }
        cpa_commit();
    };

    fill(0); fill(1);

    for (int c = 0; c < 32; c++){
        if (c < 31) asm volatile("cp.async.wait_group 1;" ::: "memory");
        else        asm volatile("cp.async.wait_group 0;" ::: "memory");
        __syncthreads();
        if (c < 30) fill(c+2);

        const float* A = stA[c%3];
        const float* B = stB[c%3];
        #pragma unroll
        for (int ks=0; ks<4; ks++){
            const int k0 = ks*8 + s;
            uint32_t bf[4][2];
            #pragma unroll
            for (int nf=0; nf<4; nf++){
                int cn = wn + nf*8 + q;
                if (BT == 0){
                    bf[nf][0] = fb(to_tf32(B[k0*136 + cn]));
                    bf[nf][1] = fb(to_tf32(B[(k0+4)*136 + cn]));
                } else {
                    bf[nf][0] = fb(to_tf32(B[cn*36 + k0]));
                    bf[nf][1] = fb(to_tf32(B[cn*36 + k0 + 4]));
                }
            }
            uint32_t af[4][4];
            #pragma unroll
            for (int mf=0; mf<4; mf++){
                int r = wm + mf*16 + q;
                af[mf][0] = fb(to_tf32(A[k0*136 + r]));
                af[mf][1] = fb(to_tf32(A[k0*136 + r + 8]));
                af[mf][2] = fb(to_tf32(A[(k0+4)*136 + r]));
                af[mf][3] = fb(to_tf32(A[(k0+4)*136 + r + 8]));
            }
            #pragma unroll
            for (int mf=0; mf<4; mf++)
                #pragma unroll
                for (int nf=0; nf<4; nf++)
                    mma8(acc[mf][nf], af[mf], bf[nf]);
        }
    }

    #pragma unroll
    for (int mf=0; mf<4; mf++){
        int M = row0 + m0 + wm + mf*16 + q;
        #pragma unroll
        for (int nf=0; nf<4; nf++){
            int N = col0 + n0 + wn + nf*8 + s*2;
            #pragma unroll
            for (int e=0; e<4; e++){
                int Mx = M + ((e>>1)<<3);
                int Nx = N + (e&1);
                g_Wp[(size_t)Nx*1024 + ((Mx>>3)<<3) + ((Mx&3)<<1) + ((Mx>>2)&1)]
                    = to_tf32(scale*acc[mf][nf][e]);
            }
        }
    }
}

// ============================================================
// K2: PV = X @ Wp^T  (R7 version, measured 250.9us).
// CTA 128x128, 256 thr, warps 2m x 4n (64x32), 3-stage cp.async,
// both operands in smem, XOR-swizzled. 2 CTAs/SM, grid (8,128).
// ============================================================
#define PV_STF 8192
#define PV_SMEM_BYTES (3*PV_STF*4)

extern __shared__ float pvsm[];

__global__ __launch_bounds__(256,2) void k_pv()
{
    const int tid = threadIdx.x, lane = tid&31, wid = tid>>5;
    const int q = lane>>2, s = lane&3;
    const int m0 = blockIdx.y*128, n0 = blockIdx.x*128;
    const int wm = (wid>>2)*64, wn = (wid&3)*32;

    float* stA[3]; float* stB[3];
    #pragma unroll
    for (int ss=0;ss<3;ss++){ stA[ss] = pvsm + ss*PV_STF; stB[ss] = stA[ss] + 4096; }

    int poff[4];
    #pragma unroll
    for (int ks=0;ks<4;ks++) poff[ks] = (((ks*2 + (s>>1)) ^ q) << 2) + ((s&1) << 1);

    float acc[4][4][4];
    #pragma unroll
    for (int a=0;a<4;a++)
        #pragma unroll
        for (int b=0;b<4;b++)
            #pragma unroll
            for (int c=0;c<4;c++) acc[a][b][c]=0.f;

    auto fill = [&](int c){
        const int si = c%3;
        float* A = stA[si]; float* B = stB[si];
        #pragma unroll
        for (int i=0;i<4;i++){
            int u = tid + 256*i;
            int r = u>>3, j = u&7;
            cpa16(smem_u32(A + r*32 + ((j ^ (r&7))<<2)),
                  g_Xp + (size_t)(m0+r)*1024 + c*32 + j*4);
        }
        #pragma unroll
        for (int i=0;i<4;i++){
            int u = tid + 256*i;
            int r = u>>3, j = u&7;
            cpa16(smem_u32(B + r*32 + ((j ^ (r&7))<<2)),
                  g_Wp + (size_t)(n0+r)*1024 + c*32 + j*4);
        }
        cpa_commit();
    };

    fill(0); fill(1);

    for (int c = 0; c < 32; c++){
        if (c < 31) asm volatile("cp.async.wait_group 1;" ::: "memory");
        else        asm volatile("cp.async.wait_group 0;" ::: "memory");
        __syncthreads();
        if (c < 30) fill(c+2);

        const float* A = stA[c%3];
        const float* B = stB[c%3];
        #pragma unroll
        for (int ks=0; ks<4; ks++){
            uint32_t bf[4][2];
            #pragma unroll
            for (int nf=0; nf<4; nf++){
                int rb = wn + nf*8 + q;
                float2 v = *(const float2*)(B + rb*32 + poff[ks]);
                bf[nf][0] = fb(v.x); bf[nf][1] = fb(v.y);
            }
            uint32_t af[4][4];
            #pragma unroll
            for (int mf=0; mf<4; mf++){
                int ra = wm + mf*16 + q;
                const float* ap = A + ra*32;
                float2 lo = *(const float2*)(ap + poff[ks]);
                float2 hi = *(const float2*)(ap + 256 + poff[ks]);
                af[mf][0] = fb(lo.x); af[mf][1] = fb(hi.x);
                af[mf][2] = fb(lo.y); af[mf][3] = fb(hi.y);
            }
            #pragma unroll
            for (int mf=0; mf<4; mf++)
                #pragma unroll
                for (int nf=0; nf<4; nf++)
                    mma8(acc[mf][nf], af[mf], bf[nf]);
        }
    }

    #pragma unroll
    for (int mf=0; mf<4; mf++){
        int m = m0 + wm + mf*16 + q;
        #pragma unroll
        for (int nf=0; nf<4; nf++){
            int n = n0 + wn + nf*8 + s*2;
            float2 v0; v0.x = acc[mf][nf][0]; v0.y = acc[mf][nf][1];
            float2 v1; v1.x = acc[mf][nf][2]; v1.y = acc[mf][nf][3];
            *(float2*)(g_PV + (size_t)m*1024 + n)     = v0;
            *(float2*)(g_PV + (size_t)(m+8)*1024 + n) = v1;
        }
    }
}

// ============================================================
// K3: per-batch attention + LN (R8 version, measured 87.0us).
// ============================================================
#define AT_LS   0
#define AT_GS   (64*68)
#define AT_BS   (AT_GS + 512)
#define AT_OV   (AT_BS + 512)
#define AT_SMEM_FLOATS (AT_OV + 8704 + 64*516)
#define AT_SMEM_BYTES  (AT_SMEM_FLOATS*4)

extern __shared__ float atsm[];

__global__ __launch_bounds__(512,1) void k_attn_tc(
    const float* __restrict__ h, const float* __restrict__ lng,
    const float* __restrict__ lnb, float* __restrict__ out)
{
    float* ls = atsm + AT_LS;
    float* gs = atsm + AT_GS;
    float* bs = atsm + AT_BS;
    float* Pc = atsm + AT_OV;
    float* hc = Pc + 64*132;
    float* Vt = atsm + AT_OV;
    float* Ob = Vt + 128*68;

    const int b = blockIdx.x;
    const int tid = threadIdx.x, lane = tid&31, wid = tid>>5;
    const int g = lane>>2, t = lane&3;
    const float* Pb = g_PV + (size_t)b*64*1024;
    const float* hb = h + (size_t)b*64*512;

    gs[tid] = lng[tid];
    bs[tid] = lnb[tid];

    const int wlm = (wid&3)*16, wln = (wid>>2)*16;
    float lacc[2][4];
    #pragma unroll
    for (int i=0;i<2;i++)
        #pragma unroll
        for (int j=0;j<4;j++) lacc[i][j]=0.f;

    for (int dc=0; dc<4; dc++){
        #pragma unroll
        for (int it=0; it<4; it++){
            int v = tid + it*512;
            int qq = v>>5, f4 = (v&31)*4;
            float4 pv = *(const float4*)(Pb + (size_t)qq*1024 + dc*128 + f4);
            float4 cv; cv.x=to_tf32(pv.x); cv.y=to_tf32(pv.y); cv.z=to_tf32(pv.z); cv.w=to_tf32(pv.w);
            *(float4*)(Pc + qq*132 + f4) = cv;
            float4 hv = *(const float4*)(hb + (size_t)qq*512 + dc*128 + f4);
            float4 ch; ch.x=to_tf32(hv.x); ch.y=to_tf32(hv.y); ch.z=to_tf32(hv.z); ch.w=to_tf32(hv.w);
            *(float4*)(hc + qq*132 + f4) = ch;
        }
        __syncthreads();
        #pragma unroll
        for (int kk=0; kk<16; kk++){
            uint32_t af[4];
            af[0] = fb(Pc[(wlm+g)*132 + kk*8 + t]);
            af[1] = fb(Pc[(wlm+g+8)*132 + kk*8 + t]);
            af[2] = fb(Pc[(wlm+g)*132 + kk*8 + t + 4]);
            af[3] = fb(Pc[(wlm+g+8)*132 + kk*8 + t + 4]);
            #pragma unroll
            for (int nf=0; nf<2; nf++){
                uint32_t bf[2];
                bf[0] = fb(hc[(wln+nf*8+g)*132 + kk*8 + t]);
                bf[1] = fb(hc[(wln+nf*8+g)*132 + kk*8 + t + 4]);
                mma8(lacc[nf], af, bf);
            }
        }
        __syncthreads();
    }
    #pragma unroll
    for (int nf=0; nf<2; nf++){
        int col = wln + nf*8 + 2*t;
        float2 v0; v0.x = lacc[nf][0]; v0.y = lacc[nf][1];
        float2 v1; v1.x = lacc[nf][2]; v1.y = lacc[nf][3];
        *(float2*)(ls + (wlm+g)*68 + col)   = v0;
        *(float2*)(ls + (wlm+g+8)*68 + col) = v1;
    }
    __syncthreads();

    #pragma unroll
    for (int i=0;i<4;i++){
        int r = wid*4 + i;
        float v0 = ls[r*68 + lane], v1 = ls[r*68 + lane + 32];
        float m = wmax(fmaxf(v0, v1));
        float e0 = __expf(v0 - m), e1 = __expf(v1 - m);
        float inv = 1.f / wsum(e0 + e1);
        ls[r*68 + lane] = e0*inv;
        ls[r*68 + lane + 32] = e1*inv;
    }
    __syncthreads();

    const int wk = wid>>2, wd = wid&3;
    for (int dc=0; dc<4; dc++){
        #pragma unroll
        for (int it=0; it<4; it++){
            int v = tid + it*512;
            int qq = v & 63, fg = (v>>6)*4;
            float4 vv = *(const float4*)(Pb + (size_t)qq*1024 + 512 + dc*128 + fg);
            Vt[(fg+0)*68 + qq] = to_tf32(vv.x);
            Vt[(fg+1)*68 + qq] = to_tf32(vv.y);
            Vt[(fg+2)*68 + qq] = to_tf32(vv.z);
            Vt[(fg+3)*68 + qq] = to_tf32(vv.w);
        }
        __syncthreads();
        float oc[4][4];
        #pragma unroll
        for (int i=0;i<4;i++)
            #pragma unroll
            for (int j=0;j<4;j++) oc[i][j]=0.f;
        #pragma unroll
        for (int kk=0; kk<8; kk++){
            uint32_t af[4];
            af[0] = fb(ls[(wk*16+g)*68 + kk*8 + t]);
            af[1] = fb(ls[(wk*16+g+8)*68 + kk*8 + t]);
            af[2] = fb(ls[(wk*16+g)*68 + kk*8 + t + 4]);
            af[3] = fb(ls[(wk*16+g+8)*68 + kk*8 + t + 4]);
            #pragma unroll
            for (int nf=0; nf<4; nf++){
                uint32_t bf[2];
                bf[0] = fb(Vt[(wd*32+nf*8+g)*68 + kk*8 + t]);
                bf[1] = fb(Vt[(wd*32+nf*8+g)*68 + kk*8 + t + 4]);
                mma8(oc[nf], af, bf);
            }
        }
        #pragma unroll
        for (int nf=0; nf<4; nf++){
            int col = dc*128 + wd*32 + nf*8 + 2*t;
            float2 v0; v0.x = oc[nf][0]; v0.y = oc[nf][1];
            float2 v1; v1.x = oc[nf][2]; v1.y = oc[nf][3];
            *(float2*)(Ob + (wk*16+g)*516 + col)   = v0;
            *(float2*)(Ob + (wk*16+g+8)*516 + col) = v1;
        }
        __syncthreads();
    }

    {
        int row = tid>>3, j = tid&7;
        const float* orow = Ob + row*516 + j*64;
        float s1=0.f, s2=0.f;
        #pragma unroll
        for (int i2=0;i2<64;i2+=4){
            float4 v = *(const float4*)(orow+i2);
            s1 += v.x+v.y+v.z+v.w;
            s2 += v.x*v.x+v.y*v.y+v.z*v.z+v.w*v.w;
        }
        #pragma unroll
        for (int o=1;o<8;o<<=1){
            s1 += __shfl_xor_sync(0xffffffffu, s1, o);
            s2 += __shfl_xor_sync(0xffffffffu, s2, o);
        }
        float mu = s1 * (1.f/512.f);
        float var = s2 * (1.f/512.f) - mu*mu;
        float rs = rsqrtf(var + 1e-5f);
        float* op = out + ((size_t)b*64 + row)*512 + j*64;
        #pragma unroll
        for (int i2=0;i2<64;i2+=4){
            float4 v = *(const float4*)(orow+i2);
            float4 gg = *(const float4*)(gs + j*64 + i2);
            float4 bb = *(const float4*)(bs + j*64 + i2);
            float4 r;
            r.x = (v.x-mu)*rs*gg.x + bb.x;
            r.y = (v.y-mu)*rs*gg.y + bb.y;
            r.z = (v.z-mu)*rs*gg.z + bb.z;
            r.w = (v.w-mu)*rs*gg.w + bb.w;
            *(float4*)(op+i2) = r;
        }
    }
}

extern "C" void kernel_launch(void* const* d_in, const int* in_sizes, int n_in,
                              void* d_out, int out_size) {
    const float* h   = (const float*)d_in[0];
    const float* z   = (const float*)d_in[1];
    const float* Whk = (const float*)d_in[2];
    const float* Whv = (const float*)d_in[3];
    const float* Wzk = (const float*)d_in[4];
    const float* Wzv = (const float*)d_in[5];
    const float* Wq  = (const float*)d_in[6];
    const float* Wo  = (const float*)d_in[7];
    const float* lng = (const float*)d_in[8];
    const float* lnb = (const float*)d_in[9];
    float* out = (float*)d_out;

    cudaFuncSetAttribute(k_fuse_tc, cudaFuncAttributeMaxDynamicSharedMemorySize, FU_SMEM_BYTES);
    cudaFuncSetAttribute(k_pv,      cudaFuncAttributeMaxDynamicSharedMemorySize, PV_SMEM_BYTES);
    cudaFuncSetAttribute(k_attn_tc, cudaFuncAttributeMaxDynamicSharedMemorySize, AT_SMEM_BYTES);

    k_prep<<<8192, 256>>>(h, z);
    k_fuse_tc<<<64, 256, FU_SMEM_BYTES>>>(Whk, Wzk, Whv, Wzv, Wq, Wo);
    k_pv<<<dim3(8,128), 256, PV_SMEM_BYTES>>>();
    k_attn_tc<<<256, 512, AT_SMEM_BYTES>>>(h, lng, lnb, out);
}